// round 1
// baseline (speedup 1.0000x reference)
#include <cuda_runtime.h>
#include <cstdint>

#define DCH 64
#define MAXN 131072

// Scratch (allocation-free rule: __device__ globals)
__device__ __align__(16) float g_buf[(size_t)MAXN * DCH];  // g = dis .* (in @ W)
__device__ __align__(16) float g_acc[(size_t)MAXN * DCH];  // scatter accumulator
__device__ float g_dis[MAXN];
__device__ int   g_deg[MAXN];

// ---------------------------------------------------------------------------
// Degree / normalization
// ---------------------------------------------------------------------------
__global__ void init_deg_kernel(int n) {
    int i = blockIdx.x * blockDim.x + threadIdx.x;
    if (i < n) g_deg[i] = 1;  // self-loop
}

__global__ void count_deg_kernel(const int* __restrict__ dst, int E) {
    int i = blockIdx.x * blockDim.x + threadIdx.x;
    if (i < E) atomicAdd(&g_deg[dst[i]], 1);
}

__global__ void dis_kernel(int n) {
    int i = blockIdx.x * blockDim.x + threadIdx.x;
    if (i < n) g_dis[i] = rsqrtf((float)g_deg[i]);
}

// ---------------------------------------------------------------------------
// Fused (finalize-prev-layer) + GEMM + scale + acc-init
//   if finalize: row = relu(dis[r]*acc_prev[r] + b_prev)  (reads g_acc)
//   else:        row = in[r]                              (layer 1: x)
//   g[r] = acc[r] = dis[r] * (row @ W)
// ---------------------------------------------------------------------------
__global__ void __launch_bounds__(256) gemm_kernel(
    const float* in, const float* __restrict__ W,
    const float* __restrict__ bprev, int n, int finalize)
{
    __shared__ float Ws[DCH * DCH];
    __shared__ float bs[DCH];
    for (int i = threadIdx.x; i < DCH * DCH; i += blockDim.x) Ws[i] = W[i];
    if (threadIdx.x < DCH) bs[threadIdx.x] = finalize ? bprev[threadIdx.x] : 0.0f;
    __syncthreads();

    int r = blockIdx.x * blockDim.x + threadIdx.x;
    if (r >= n) return;

    float dr = g_dis[r];
    float xr[DCH];

    const float4* inr = finalize
        ? (const float4*)(g_acc + (size_t)r * DCH)
        : (const float4*)(in + (size_t)r * DCH);

#pragma unroll
    for (int k4 = 0; k4 < DCH / 4; k4++) {
        float4 v = inr[k4];
        if (finalize) {
            v.x = fmaxf(fmaf(dr, v.x, bs[4 * k4 + 0]), 0.0f);
            v.y = fmaxf(fmaf(dr, v.y, bs[4 * k4 + 1]), 0.0f);
            v.z = fmaxf(fmaf(dr, v.z, bs[4 * k4 + 2]), 0.0f);
            v.w = fmaxf(fmaf(dr, v.w, bs[4 * k4 + 3]), 0.0f);
        }
        xr[4 * k4 + 0] = v.x; xr[4 * k4 + 1] = v.y;
        xr[4 * k4 + 2] = v.z; xr[4 * k4 + 3] = v.w;
    }

    float4* gout = (float4*)(g_buf + (size_t)r * DCH);
    float4* aout = (float4*)(g_acc + (size_t)r * DCH);

#pragma unroll 1
    for (int jt = 0; jt < DCH / 4; jt++) {
        float sx = 0.f, sy = 0.f, sz = 0.f, sw = 0.f;
        const float4* wcol = (const float4*)Ws + jt;
#pragma unroll
        for (int k = 0; k < DCH; k++) {
            float4 w = wcol[k * (DCH / 4)];   // uniform address -> LDS broadcast
            sx = fmaf(xr[k], w.x, sx);
            sy = fmaf(xr[k], w.y, sy);
            sz = fmaf(xr[k], w.z, sz);
            sw = fmaf(xr[k], w.w, sw);
        }
        float4 o;
        o.x = dr * sx; o.y = dr * sy; o.z = dr * sz; o.w = dr * sw;
        gout[jt] = o;   // g for the scatter
        aout[jt] = o;   // acc initialized with self-loop contribution
    }
}

// ---------------------------------------------------------------------------
// Scatter: acc[dst] += g[src]   (half-warp per edge, vector red, no return)
// ---------------------------------------------------------------------------
__global__ void __launch_bounds__(256) scatter_kernel(
    const int* __restrict__ src, const int* __restrict__ dst, int E)
{
    int t = blockIdx.x * blockDim.x + threadIdx.x;
    int e = t >> 4;
    if (e >= E) return;
    int c = (t & 15) << 2;
    int s = __ldg(src + e);
    int d = __ldg(dst + e);
    float4 v = *(const float4*)(g_buf + (size_t)s * DCH + c);
    float* p = g_acc + (size_t)d * DCH + c;
    asm volatile("red.global.add.v4.f32 [%0], {%1, %2, %3, %4};"
                 :: "l"(p), "f"(v.x), "f"(v.y), "f"(v.z), "f"(v.w)
                 : "memory");
}

// ---------------------------------------------------------------------------
// Final output: out = dis .* acc + b3
// ---------------------------------------------------------------------------
__global__ void __launch_bounds__(256) out_kernel(
    const float* __restrict__ b, float* __restrict__ out, int n)
{
    int t = blockIdx.x * blockDim.x + threadIdx.x;
    int r = t >> 4;
    if (r >= n) return;
    int c = (t & 15) << 2;
    float dr = g_dis[r];
    float4 v  = *(const float4*)(g_acc + (size_t)r * DCH + c);
    float4 bb = *(const float4*)(b + c);
    float4 o;
    o.x = fmaf(dr, v.x, bb.x);
    o.y = fmaf(dr, v.y, bb.y);
    o.z = fmaf(dr, v.z, bb.z);
    o.w = fmaf(dr, v.w, bb.w);
    *(float4*)(out + (size_t)r * DCH + c) = o;
}

// ---------------------------------------------------------------------------
extern "C" void kernel_launch(void* const* d_in, const int* in_sizes, int n_in,
                              void* d_out, int out_size)
{
    const float* x  = (const float*)d_in[0];
    const int*   ei = (const int*)d_in[1];
    const float* W1 = (const float*)d_in[2];
    const float* b1 = (const float*)d_in[3];
    const float* W2 = (const float*)d_in[4];
    const float* b2 = (const float*)d_in[5];
    const float* W3 = (const float*)d_in[6];
    const float* b3 = (const float*)d_in[7];
    float* out = (float*)d_out;

    int n = in_sizes[0] / DCH;
    int E = in_sizes[1] / 2;
    const int* src = ei;
    const int* dst = ei + E;

    int nb_n   = (n + 255) / 256;
    int nb_e   = (E + 255) / 256;
    int nb_sc  = (int)(((long long)E * 16 + 255) / 256);
    int nb_out = (int)(((long long)n * 16 + 255) / 256);

    // degree / normalization (recomputed every call: no caching)
    init_deg_kernel<<<nb_n, 256>>>(n);
    count_deg_kernel<<<nb_e, 256>>>(dst, E);
    dis_kernel<<<nb_n, 256>>>(n);

    // layer 1
    gemm_kernel<<<nb_n, 256>>>(x, W1, b1 /*unused*/, n, 0);
    scatter_kernel<<<nb_sc, 256>>>(src, dst, E);
    // layer 2 (finalize L1: relu(dis*acc + b1), then GEMM W2)
    gemm_kernel<<<nb_n, 256>>>(nullptr, W2, b1, n, 1);
    scatter_kernel<<<nb_sc, 256>>>(src, dst, E);
    // layer 3 (finalize L2: relu(dis*acc + b2), then GEMM W3)
    gemm_kernel<<<nb_n, 256>>>(nullptr, W3, b2, n, 1);
    scatter_kernel<<<nb_sc, 256>>>(src, dst, E);
    // output
    out_kernel<<<nb_out, 256>>>(b3, out, n);
}

// round 2
// speedup vs baseline: 2.0238x; 2.0238x over previous
#include <cuda_runtime.h>
#include <cstdint>

#define DCH 64
#define MAXN 131072
#define MAXE (1 << 21)

// Scratch (allocation-free rule: __device__ globals)
__device__ __align__(16) float g_buf[(size_t)MAXN * DCH];  // g = dis .* (h @ W)
__device__ __align__(16) float g_acc[(size_t)MAXN * DCH];  // gathered sums
__device__ float g_dis[MAXN];
__device__ int   g_degE[MAXN];
__device__ int   g_rowptr[MAXN + 1];
__device__ int   g_cursor[MAXN];
__device__ int   g_col[MAXE];
__device__ int   g_bsum[256];

// ---------------------------------------------------------------------------
// Degree / normalization
// ---------------------------------------------------------------------------
__global__ void zero_deg_kernel(int n) {
    int i = blockIdx.x * blockDim.x + threadIdx.x;
    if (i < n) g_degE[i] = 0;
}
__global__ void count_deg_kernel(const int* __restrict__ dst, int E) {
    int i = blockIdx.x * blockDim.x + threadIdx.x;
    if (i < E) atomicAdd(&g_degE[dst[i]], 1);
}
__global__ void dis_kernel(int n) {
    int i = blockIdx.x * blockDim.x + threadIdx.x;
    if (i < n) g_dis[i] = rsqrtf((float)(g_degE[i] + 1));  // +1 self-loop
}

// ---------------------------------------------------------------------------
// CSR build: exclusive scan of edge-degrees (1024 elems / block)
// ---------------------------------------------------------------------------
__global__ void scanA_kernel(int n) {
    __shared__ int sh[256];
    int base = blockIdx.x * 1024 + threadIdx.x * 4;
    int s = 0;
#pragma unroll
    for (int i = 0; i < 4; i++) s += (base + i < n) ? g_degE[base + i] : 0;
    sh[threadIdx.x] = s;
    __syncthreads();
    for (int off = 128; off; off >>= 1) {
        if (threadIdx.x < off) sh[threadIdx.x] += sh[threadIdx.x + off];
        __syncthreads();
    }
    if (threadIdx.x == 0) g_bsum[blockIdx.x] = sh[0];
}
__global__ void scanB_kernel(int nb, int n, int E) {
    if (threadIdx.x == 0 && blockIdx.x == 0) {
        int run = 0;
        for (int i = 0; i < nb; i++) { int v = g_bsum[i]; g_bsum[i] = run; run += v; }
        g_rowptr[n] = E;
    }
}
__global__ void scanC_kernel(int n) {
    __shared__ int sh[256];
    int base = blockIdx.x * 1024 + threadIdx.x * 4;
    int v[4]; int mysum = 0;
#pragma unroll
    for (int i = 0; i < 4; i++) {
        v[i] = (base + i < n) ? g_degE[base + i] : 0;
        mysum += v[i];
    }
    sh[threadIdx.x] = mysum;
    __syncthreads();
    for (int off = 1; off < 256; off <<= 1) {
        int t = (threadIdx.x >= off) ? sh[threadIdx.x - off] : 0;
        __syncthreads();
        sh[threadIdx.x] += t;
        __syncthreads();
    }
    int run = sh[threadIdx.x] - mysum + g_bsum[blockIdx.x];
#pragma unroll
    for (int i = 0; i < 4; i++) {
        if (base + i < n) {
            g_rowptr[base + i] = run;
            g_cursor[base + i] = run;
            run += v[i];
        }
    }
}
__global__ void fill_kernel(const int* __restrict__ src, const int* __restrict__ dst, int E) {
    int e = blockIdx.x * blockDim.x + threadIdx.x;
    if (e < E) {
        int pos = atomicAdd(&g_cursor[dst[e]], 1);
        g_col[pos] = src[e];
    }
}

// ---------------------------------------------------------------------------
// Tiled GEMM: BM=128, N=K=64. 256 threads; thread = 8 rows x 4 cols.
//   row = finalize ? relu(dis[r]*acc[r] + bprev) : in[r]
//   g_buf[r] = dis[r] * (row @ W)
// ---------------------------------------------------------------------------
__global__ void __launch_bounds__(256) gemm_kernel(
    const float* in, const float* __restrict__ W,
    const float* __restrict__ bprev, int n, int finalize)
{
    __shared__ float xs[128 * DCH];   // 32 KB
    __shared__ float Ws[DCH * DCH];   // 16 KB
    int tid = threadIdx.x;

    // stage W
#pragma unroll
    for (int i = 0; i < 4; i++)
        ((float4*)Ws)[tid + 256 * i] = ((const float4*)W)[tid + 256 * i];

    // stage x tile (with fused finalize of previous layer)
    int base = blockIdx.x * 128;
    int cg = (tid & 15) * 4;
    float4 bb = finalize ? *(const float4*)(bprev + cg) : make_float4(0.f, 0.f, 0.f, 0.f);
#pragma unroll
    for (int rep = 0; rep < 8; rep++) {
        int lr = (tid >> 4) + rep * 16;
        int r = base + lr;
        float4 v = make_float4(0.f, 0.f, 0.f, 0.f);
        if (r < n) {
            if (finalize) {
                v = *(const float4*)(g_acc + (size_t)r * DCH + cg);
                float dr = g_dis[r];
                v.x = fmaxf(fmaf(dr, v.x, bb.x), 0.f);
                v.y = fmaxf(fmaf(dr, v.y, bb.y), 0.f);
                v.z = fmaxf(fmaf(dr, v.z, bb.z), 0.f);
                v.w = fmaxf(fmaf(dr, v.w, bb.w), 0.f);
            } else {
                v = *(const float4*)(in + (size_t)r * DCH + cg);
            }
        }
        *(float4*)(xs + lr * DCH + cg) = v;
    }
    __syncthreads();

    // compute 8 rows x 4 cols per thread
    int rbase = (tid >> 4) * 8;
    float4 acc[8];
#pragma unroll
    for (int i = 0; i < 8; i++) acc[i] = make_float4(0.f, 0.f, 0.f, 0.f);

#pragma unroll 8
    for (int k = 0; k < DCH; k++) {
        float4 w = *(const float4*)(Ws + k * DCH + cg);
#pragma unroll
        for (int i = 0; i < 8; i++) {
            float xv = xs[(rbase + i) * DCH + k];
            acc[i].x = fmaf(xv, w.x, acc[i].x);
            acc[i].y = fmaf(xv, w.y, acc[i].y);
            acc[i].z = fmaf(xv, w.z, acc[i].z);
            acc[i].w = fmaf(xv, w.w, acc[i].w);
        }
    }

#pragma unroll
    for (int i = 0; i < 8; i++) {
        int r = base + rbase + i;
        if (r < n) {
            float dr = g_dis[r];
            float4 o;
            o.x = dr * acc[i].x; o.y = dr * acc[i].y;
            o.z = dr * acc[i].z; o.w = dr * acc[i].w;
            *(float4*)(g_buf + (size_t)r * DCH + cg) = o;
        }
    }
}

// ---------------------------------------------------------------------------
// CSR gather: acc[r] = g_buf[r] + sum_{e in in(r)} g_buf[col[e]]
// 16 threads per node, float4 per thread.
// ---------------------------------------------------------------------------
__global__ void __launch_bounds__(256) gather_kernel(int n)
{
    int t = blockIdx.x * blockDim.x + threadIdx.x;
    int r = t >> 4;
    if (r >= n) return;
    int c4 = t & 15;

    const float4* gb = (const float4*)g_buf;
    float4 a = gb[(size_t)r * 16 + c4];  // self-loop term
    int e0 = g_rowptr[r], e1 = g_rowptr[r + 1];
    for (int e = e0; e < e1; e++) {
        int s = __ldg(&g_col[e]);
        float4 v = gb[(size_t)s * 16 + c4];
        a.x += v.x; a.y += v.y; a.z += v.z; a.w += v.w;
    }
    ((float4*)g_acc)[(size_t)r * 16 + c4] = a;
}

// ---------------------------------------------------------------------------
// Final output: out = dis .* acc + b3
// ---------------------------------------------------------------------------
__global__ void __launch_bounds__(256) out_kernel(
    const float* __restrict__ b, float* __restrict__ out, int n)
{
    int t = blockIdx.x * blockDim.x + threadIdx.x;
    int r = t >> 4;
    if (r >= n) return;
    int c = (t & 15) << 2;
    float dr = g_dis[r];
    float4 v  = *(const float4*)(g_acc + (size_t)r * DCH + c);
    float4 bb = *(const float4*)(b + c);
    float4 o;
    o.x = fmaf(dr, v.x, bb.x);
    o.y = fmaf(dr, v.y, bb.y);
    o.z = fmaf(dr, v.z, bb.z);
    o.w = fmaf(dr, v.w, bb.w);
    *(float4*)(out + (size_t)r * DCH + c) = o;
}

// ---------------------------------------------------------------------------
extern "C" void kernel_launch(void* const* d_in, const int* in_sizes, int n_in,
                              void* d_out, int out_size)
{
    const float* x  = (const float*)d_in[0];
    const int*   ei = (const int*)d_in[1];
    const float* W1 = (const float*)d_in[2];
    const float* b1 = (const float*)d_in[3];
    const float* W2 = (const float*)d_in[4];
    const float* b2 = (const float*)d_in[5];
    const float* W3 = (const float*)d_in[6];
    const float* b3 = (const float*)d_in[7];
    float* out = (float*)d_out;

    int n = in_sizes[0] / DCH;
    int E = in_sizes[1] / 2;
    const int* src = ei;
    const int* dst = ei + E;

    int nb_n   = (n + 255) / 256;
    int nb_e   = (E + 255) / 256;
    int nb_sc  = (n + 1023) / 1024;
    int nb_gm  = (n + 127) / 128;
    int nb_gat = (int)(((long long)n * 16 + 255) / 256);

    // normalization + CSR build (recomputed every call)
    zero_deg_kernel<<<nb_n, 256>>>(n);
    count_deg_kernel<<<nb_e, 256>>>(dst, E);
    dis_kernel<<<nb_n, 256>>>(n);
    scanA_kernel<<<nb_sc, 256>>>(n);
    scanB_kernel<<<1, 32>>>(nb_sc, n, E);
    scanC_kernel<<<nb_sc, 256>>>(n);
    fill_kernel<<<nb_e, 256>>>(src, dst, E);

    // layer 1
    gemm_kernel<<<nb_gm, 256>>>(x, W1, b1 /*unused*/, n, 0);
    gather_kernel<<<nb_gat, 256>>>(n);
    // layer 2
    gemm_kernel<<<nb_gm, 256>>>(nullptr, W2, b1, n, 1);
    gather_kernel<<<nb_gat, 256>>>(n);
    // layer 3
    gemm_kernel<<<nb_gm, 256>>>(nullptr, W3, b2, n, 1);
    gather_kernel<<<nb_gat, 256>>>(n);
    // output
    out_kernel<<<nb_gat, 256>>>(b3, out, n);
}

// round 5
// speedup vs baseline: 2.2903x; 1.1317x over previous
#include <cuda_runtime.h>
#include <cuda_fp16.h>
#include <cstdint>

#define DCH 64
#define MAXN 131072
#define MAXE (1 << 21)

// Scratch (allocation-free rule: __device__ globals)
__device__ __align__(16) __half g_bufh[(size_t)MAXN * DCH]; // fp16 messages
__device__ __align__(16) float  g_acc[(size_t)MAXN * DCH];  // gathered sums (fp32)
__device__ float g_dis[MAXN];
__device__ int   g_degE[MAXN];
__device__ int   g_rowptr[MAXN + 1];
__device__ int   g_cursor[MAXN];
__device__ int   g_col[MAXE];
__device__ int   g_bsum[256];

// ---------------------------------------------------------------------------
// Degree / normalization + CSR build
// ---------------------------------------------------------------------------
__global__ void count_deg_kernel(const int* __restrict__ dst, int E) {
    int i = blockIdx.x * blockDim.x + threadIdx.x;
    if (i < E) atomicAdd(&g_degE[dst[i]], 1);
}
// per-1024-chunk sums for the scan; also computes dis = rsqrt(deg+1)
__global__ void scanA_kernel(int n) {
    __shared__ int sh[256];
    int base = blockIdx.x * 1024 + threadIdx.x * 4;
    int s = 0;
#pragma unroll
    for (int i = 0; i < 4; i++) {
        int idx = base + i;
        if (idx < n) {
            int d = g_degE[idx];
            s += d;
            g_dis[idx] = rsqrtf((float)(d + 1));
        }
    }
    sh[threadIdx.x] = s;
    __syncthreads();
    for (int off = 128; off; off >>= 1) {
        if (threadIdx.x < off) sh[threadIdx.x] += sh[threadIdx.x + off];
        __syncthreads();
    }
    if (threadIdx.x == 0) g_bsum[blockIdx.x] = sh[0];
}
__global__ void scanB_kernel(int nb, int n, int E) {
    if (threadIdx.x == 0 && blockIdx.x == 0) {
        int run = 0;
        for (int i = 0; i < nb; i++) { int v = g_bsum[i]; g_bsum[i] = run; run += v; }
        g_rowptr[n] = E;
    }
}
__global__ void scanC_kernel(int n) {
    __shared__ int sh[256];
    int base = blockIdx.x * 1024 + threadIdx.x * 4;
    int v[4]; int mysum = 0;
#pragma unroll
    for (int i = 0; i < 4; i++) {
        v[i] = (base + i < n) ? g_degE[base + i] : 0;
        mysum += v[i];
    }
    sh[threadIdx.x] = mysum;
    __syncthreads();
    for (int off = 1; off < 256; off <<= 1) {
        int t = (threadIdx.x >= off) ? sh[threadIdx.x - off] : 0;
        __syncthreads();
        sh[threadIdx.x] += t;
        __syncthreads();
    }
    int run = sh[threadIdx.x] - mysum + g_bsum[blockIdx.x];
#pragma unroll
    for (int i = 0; i < 4; i++) {
        if (base + i < n) {
            g_rowptr[base + i] = run;
            g_cursor[base + i] = run;
            run += v[i];
        }
    }
}
__global__ void fill_kernel(const int* __restrict__ src, const int* __restrict__ dst, int E) {
    int e = blockIdx.x * blockDim.x + threadIdx.x;
    if (e < E) {
        int pos = atomicAdd(&g_cursor[dst[e]], 1);
        g_col[pos] = src[e];
    }
}

// ---------------------------------------------------------------------------
// Tiled GEMM: BM=128, N=K=64. 256 threads; thread = 8 rows x 4 cols.
//   row = finalize ? relu(dis[r]*acc[r] + bprev) : in[r]
//   g_bufh[r] = fp16( dis[r] * (row @ W) )
// ---------------------------------------------------------------------------
__global__ void __launch_bounds__(256) gemm_kernel(
    const float* in, const float* __restrict__ W,
    const float* __restrict__ bprev, int n, int finalize)
{
    __shared__ float xs[128 * DCH];   // 32 KB
    __shared__ float Ws[DCH * DCH];   // 16 KB
    int tid = threadIdx.x;

    // stage W
#pragma unroll
    for (int i = 0; i < 4; i++)
        ((float4*)Ws)[tid + 256 * i] = ((const float4*)W)[tid + 256 * i];

    // stage x tile (with fused finalize of previous layer)
    int base = blockIdx.x * 128;
    int cg = (tid & 15) * 4;
    float4 bb = finalize ? *(const float4*)(bprev + cg) : make_float4(0.f, 0.f, 0.f, 0.f);
#pragma unroll
    for (int rep = 0; rep < 8; rep++) {
        int lr = (tid >> 4) + rep * 16;
        int r = base + lr;
        float4 v = make_float4(0.f, 0.f, 0.f, 0.f);
        if (r < n) {
            if (finalize) {
                v = *(const float4*)(g_acc + (size_t)r * DCH + cg);
                float dr = g_dis[r];
                v.x = fmaxf(fmaf(dr, v.x, bb.x), 0.f);
                v.y = fmaxf(fmaf(dr, v.y, bb.y), 0.f);
                v.z = fmaxf(fmaf(dr, v.z, bb.z), 0.f);
                v.w = fmaxf(fmaf(dr, v.w, bb.w), 0.f);
            } else {
                v = *(const float4*)(in + (size_t)r * DCH + cg);
            }
        }
        *(float4*)(xs + lr * DCH + cg) = v;
    }
    __syncthreads();

    // compute 8 rows x 4 cols per thread
    int rbase = (tid >> 4) * 8;
    float4 acc[8];
#pragma unroll
    for (int i = 0; i < 8; i++) acc[i] = make_float4(0.f, 0.f, 0.f, 0.f);

#pragma unroll 8
    for (int k = 0; k < DCH; k++) {
        float4 w = *(const float4*)(Ws + k * DCH + cg);
#pragma unroll
        for (int i = 0; i < 8; i++) {
            float xv = xs[(rbase + i) * DCH + k];
            acc[i].x = fmaf(xv, w.x, acc[i].x);
            acc[i].y = fmaf(xv, w.y, acc[i].y);
            acc[i].z = fmaf(xv, w.z, acc[i].z);
            acc[i].w = fmaf(xv, w.w, acc[i].w);
        }
    }

#pragma unroll
    for (int i = 0; i < 8; i++) {
        int r = base + rbase + i;
        if (r < n) {
            float dr = g_dis[r];
            __half2 h0 = __floats2half2_rn(dr * acc[i].x, dr * acc[i].y);
            __half2 h1 = __floats2half2_rn(dr * acc[i].z, dr * acc[i].w);
            uint32_t u0 = *(uint32_t*)&h0;
            uint32_t u1 = *(uint32_t*)&h1;
            *(uint2*)(g_bufh + (size_t)r * DCH + cg) = make_uint2(u0, u1);
        }
    }
}

// ---------------------------------------------------------------------------
// CSR gather (fp16 messages, fp32 accumulate).
// 8 threads per node, each owns 8 channels (one uint4 = 128b of fp16).
//   final==0: g_acc[r] = sum (fp32)
//   final==1: out[r]   = dis[r]*sum + b
// ---------------------------------------------------------------------------
__device__ __forceinline__ void acc_h8(float* a, uint4 v) {
    __half2 h0 = *(__half2*)&v.x, h1 = *(__half2*)&v.y;
    __half2 h2 = *(__half2*)&v.z, h3 = *(__half2*)&v.w;
    float2 f0 = __half22float2(h0), f1 = __half22float2(h1);
    float2 f2 = __half22float2(h2), f3 = __half22float2(h3);
    a[0] += f0.x; a[1] += f0.y; a[2] += f1.x; a[3] += f1.y;
    a[4] += f2.x; a[5] += f2.y; a[6] += f3.x; a[7] += f3.y;
}

__global__ void __launch_bounds__(256) gather_kernel(
    const float* __restrict__ b, float* __restrict__ out, int n, int final_layer)
{
    int t = blockIdx.x * blockDim.x + threadIdx.x;
    int r = t >> 3;
    if (r >= n) return;
    int c = t & 7;   // owns channels [c*8, c*8+8)

    const uint4* gb = (const uint4*)g_bufh;   // 8 uint4 per row
    float a[8] = {0, 0, 0, 0, 0, 0, 0, 0};
    acc_h8(a, gb[(size_t)r * 8 + c]);         // self-loop term

    int e0 = g_rowptr[r], e1 = g_rowptr[r + 1];
#pragma unroll 4
    for (int e = e0; e < e1; e++) {
        int s = __ldg(&g_col[e]);
        acc_h8(a, gb[(size_t)s * 8 + c]);
    }

    if (final_layer) {
        float dr = g_dis[r];
        float4 b0 = *(const float4*)(b + c * 8);
        float4 b1 = *(const float4*)(b + c * 8 + 4);
        float4 o0, o1;
        o0.x = fmaf(dr, a[0], b0.x); o0.y = fmaf(dr, a[1], b0.y);
        o0.z = fmaf(dr, a[2], b0.z); o0.w = fmaf(dr, a[3], b0.w);
        o1.x = fmaf(dr, a[4], b1.x); o1.y = fmaf(dr, a[5], b1.y);
        o1.z = fmaf(dr, a[6], b1.z); o1.w = fmaf(dr, a[7], b1.w);
        *(float4*)(out + (size_t)r * DCH + c * 8)     = o0;
        *(float4*)(out + (size_t)r * DCH + c * 8 + 4) = o1;
    } else {
        float4* ao = (float4*)(g_acc + (size_t)r * DCH + c * 8);
        ao[0] = make_float4(a[0], a[1], a[2], a[3]);
        ao[1] = make_float4(a[4], a[5], a[6], a[7]);
    }
}

// ---------------------------------------------------------------------------
extern "C" void kernel_launch(void* const* d_in, const int* in_sizes, int n_in,
                              void* d_out, int out_size)
{
    const float* x  = (const float*)d_in[0];
    const int*   ei = (const int*)d_in[1];
    const float* W1 = (const float*)d_in[2];
    const float* b1 = (const float*)d_in[3];
    const float* W2 = (const float*)d_in[4];
    const float* b2 = (const float*)d_in[5];
    const float* W3 = (const float*)d_in[6];
    const float* b3 = (const float*)d_in[7];
    float* out = (float*)d_out;

    int n = in_sizes[0] / DCH;
    int E = in_sizes[1] / 2;
    const int* src = ei;
    const int* dst = ei + E;

    int nb_e   = (E + 255) / 256;
    int nb_sc  = (n + 1023) / 1024;
    int nb_gm  = (n + 127) / 128;
    int nb_gat = (int)(((long long)n * 8 + 255) / 256);

    // normalization + CSR build (recomputed every call)
    void* degE_ptr = nullptr;
    cudaGetSymbolAddress(&degE_ptr, g_degE);
    cudaMemsetAsync(degE_ptr, 0, (size_t)n * sizeof(int));
    count_deg_kernel<<<nb_e, 256>>>(dst, E);
    scanA_kernel<<<nb_sc, 256>>>(n);           // also computes g_dis
    scanB_kernel<<<1, 32>>>(nb_sc, n, E);
    scanC_kernel<<<nb_sc, 256>>>(n);
    fill_kernel<<<nb_e, 256>>>(src, dst, E);

    // layer 1
    gemm_kernel<<<nb_gm, 256>>>(x, W1, b1 /*unused*/, n, 0);
    gather_kernel<<<nb_gat, 256>>>(nullptr, nullptr, n, 0);
    // layer 2
    gemm_kernel<<<nb_gm, 256>>>(nullptr, W2, b1, n, 1);
    gather_kernel<<<nb_gat, 256>>>(nullptr, nullptr, n, 0);
    // layer 3 (gather fused with bias -> writes d_out)
    gemm_kernel<<<nb_gm, 256>>>(nullptr, W3, b2, n, 1);
    gather_kernel<<<nb_gat, 256>>>(b3, out, n, 1);
}